// round 2
// baseline (speedup 1.0000x reference)
#include <cuda_runtime.h>
#include <math_constants.h>
#include <cstdint>

namespace {
constexpr int B_ = 2, S_ = 4096, D_ = 512, H_ = 8, DH = 64;
constexpr int MR = B_ * S_;
constexpr long long SA_ELEMS = (long long)MR * D_;
}

__device__ float g_q[MR * D_];
__device__ float g_k[MR * D_];
__device__ float g_v[MR * D_];
__device__ float g_ctx[MR * D_];
__device__ float g_m[H_ * B_ * S_];
__device__ float g_l[H_ * B_ * S_];

// ---------------------------------------------------------------------------
// tf32 helpers
// ---------------------------------------------------------------------------
__device__ __forceinline__ uint32_t f2tf32(float x) {
    uint32_t r;
    asm("cvt.rna.tf32.f32 %0, %1;" : "=r"(r) : "f"(x));
    return r;
}
__device__ __forceinline__ void split_tf32(float x, uint32_t& hi, uint32_t& lo) {
    hi = f2tf32(x);
    lo = f2tf32(x - __uint_as_float(hi));
}
__device__ __forceinline__ void mma8(float* d, const uint32_t* a, const uint32_t* b) {
    asm volatile(
        "mma.sync.aligned.m16n8k8.row.col.f32.tf32.tf32.f32 "
        "{%0,%1,%2,%3}, {%4,%5,%6,%7}, {%8,%9}, {%0,%1,%2,%3};"
        : "+f"(d[0]), "+f"(d[1]), "+f"(d[2]), "+f"(d[3])
        : "r"(a[0]), "r"(a[1]), "r"(a[2]), "r"(a[3]), "r"(b[0]), "r"(b[1]));
}

// ---------------------------------------------------------------------------
// Scores: raw[z] = (Q_z @ K_z^T) / 8, full SxS (pre-mask), 3xTF32 precision.
// Block tile 128x64, 8 warps (4m x 2n), warp tile 32x32.
// smem: Ah/Al [64][132] (k-major, padded), Bh/Bl [64][68].
// ---------------------------------------------------------------------------
__global__ __launch_bounds__(256, 2)
void scores_kernel(const float* __restrict__ Q, const float* __restrict__ K,
                   float* __restrict__ raw)
{
    extern __shared__ uint32_t smbuf[];
    uint32_t* Ah = smbuf;
    uint32_t* Al = Ah + 64 * 132;
    uint32_t* Bh = Al + 64 * 132;
    uint32_t* Bl = Bh + 64 * 68;

    const int tid = threadIdx.x;
    const int z = blockIdx.z, h = z >> 1, b = z & 1;
    const int m0 = blockIdx.y * 128;
    const int n0 = blockIdx.x * 64;
    const size_t qoff = (size_t)b * S_ * D_ + (size_t)h * DH;

    // ---- load + split tiles ----
    {
        const int r0 = tid >> 4;
        const int c4 = (tid & 15) * 4;
        #pragma unroll
        for (int p = 0; p < 8; p++) {
            const int r = r0 + p * 16;
            const float4 v = *reinterpret_cast<const float4*>(
                &Q[qoff + (size_t)(m0 + r) * D_ + c4]);
            uint32_t hi, lo;
            split_tf32(v.x, hi, lo); Ah[(c4 + 0) * 132 + r] = hi; Al[(c4 + 0) * 132 + r] = lo;
            split_tf32(v.y, hi, lo); Ah[(c4 + 1) * 132 + r] = hi; Al[(c4 + 1) * 132 + r] = lo;
            split_tf32(v.z, hi, lo); Ah[(c4 + 2) * 132 + r] = hi; Al[(c4 + 2) * 132 + r] = lo;
            split_tf32(v.w, hi, lo); Ah[(c4 + 3) * 132 + r] = hi; Al[(c4 + 3) * 132 + r] = lo;
        }
        #pragma unroll
        for (int p = 0; p < 4; p++) {
            const int r = r0 + p * 16;
            const float4 v = *reinterpret_cast<const float4*>(
                &K[qoff + (size_t)(n0 + r) * D_ + c4]);
            uint32_t hi, lo;
            split_tf32(v.x, hi, lo); Bh[(c4 + 0) * 68 + r] = hi; Bl[(c4 + 0) * 68 + r] = lo;
            split_tf32(v.y, hi, lo); Bh[(c4 + 1) * 68 + r] = hi; Bl[(c4 + 1) * 68 + r] = lo;
            split_tf32(v.z, hi, lo); Bh[(c4 + 2) * 68 + r] = hi; Bl[(c4 + 2) * 68 + r] = lo;
            split_tf32(v.w, hi, lo); Bh[(c4 + 3) * 68 + r] = hi; Bl[(c4 + 3) * 68 + r] = lo;
        }
    }
    __syncthreads();

    const int lane = tid & 31, g = lane >> 2, tg = lane & 3;
    const int wid = tid >> 5, wm = wid & 3, wn = wid >> 2;

    float acc[2][4][4];
    #pragma unroll
    for (int i = 0; i < 2; i++)
        #pragma unroll
        for (int j = 0; j < 4; j++)
            #pragma unroll
            for (int t = 0; t < 4; t++) acc[i][j][t] = 0.f;

    #pragma unroll
    for (int ks = 0; ks < 8; ks++) {
        const int kb = ks * 8;
        uint32_t ah[2][4], al[2][4], bh[4][2], bl[4][2];
        #pragma unroll
        for (int mf = 0; mf < 2; mf++) {
            const int m = wm * 32 + mf * 16;
            ah[mf][0] = Ah[(kb + tg) * 132 + m + g];
            ah[mf][1] = Ah[(kb + tg) * 132 + m + 8 + g];
            ah[mf][2] = Ah[(kb + tg + 4) * 132 + m + g];
            ah[mf][3] = Ah[(kb + tg + 4) * 132 + m + 8 + g];
            al[mf][0] = Al[(kb + tg) * 132 + m + g];
            al[mf][1] = Al[(kb + tg) * 132 + m + 8 + g];
            al[mf][2] = Al[(kb + tg + 4) * 132 + m + g];
            al[mf][3] = Al[(kb + tg + 4) * 132 + m + 8 + g];
        }
        #pragma unroll
        for (int nf = 0; nf < 4; nf++) {
            const int n = wn * 32 + nf * 8 + g;
            bh[nf][0] = Bh[(kb + tg) * 68 + n];
            bh[nf][1] = Bh[(kb + tg + 4) * 68 + n];
            bl[nf][0] = Bl[(kb + tg) * 68 + n];
            bl[nf][1] = Bl[(kb + tg + 4) * 68 + n];
        }
        #pragma unroll
        for (int mf = 0; mf < 2; mf++)
            #pragma unroll
            for (int nf = 0; nf < 4; nf++) {
                mma8(acc[mf][nf], ah[mf], bh[nf]);
                mma8(acc[mf][nf], al[mf], bh[nf]);
                mma8(acc[mf][nf], ah[mf], bl[nf]);
            }
    }

    float* out = raw + (size_t)z * S_ * S_;
    #pragma unroll
    for (int mf = 0; mf < 2; mf++) {
        const int rbase = m0 + wm * 32 + mf * 16 + g;
        #pragma unroll
        for (int nf = 0; nf < 4; nf++) {
            const int c = n0 + wn * 32 + nf * 8 + 2 * tg;
            float2 v0 = make_float2(acc[mf][nf][0] * 0.125f, acc[mf][nf][1] * 0.125f);
            float2 v1 = make_float2(acc[mf][nf][2] * 0.125f, acc[mf][nf][3] * 0.125f);
            *reinterpret_cast<float2*>(&out[(size_t)rbase * S_ + c]) = v0;
            *reinterpret_cast<float2*>(&out[(size_t)(rbase + 8) * S_ + c]) = v1;
        }
    }
}

// ---------------------------------------------------------------------------
// PV: ctx = softmax(raw) @ V, causal k-range, tensor-core tf32 (P 1x, V hi/lo).
// Block tile 128x64 (full DH), 8 warps (4m x 2n), BK=64.
// ---------------------------------------------------------------------------
__global__ __launch_bounds__(256, 2)
void pv_kernel(const float* __restrict__ raw, const float* __restrict__ V,
               const float* __restrict__ rm, const float* __restrict__ rl,
               float* __restrict__ ctx)
{
    extern __shared__ uint32_t smbuf[];
    uint32_t* Ph = smbuf;                 // [64][132]
    uint32_t* Vh = Ph + 64 * 132;         // [64][68]
    uint32_t* Vl = Vh + 64 * 68;
    float* s_m  = (float*)(Vl + 64 * 68); // [128]
    float* s_il = s_m + 128;

    const int tid = threadIdx.x;
    const int z = blockIdx.z, h = z >> 1, b = z & 1;
    const int m0 = (gridDim.y - 1 - blockIdx.y) * 128;  // heavy tiles first
    const size_t roff = (size_t)z * S_ * S_;
    const size_t voff = (size_t)b * S_ * D_ + (size_t)h * DH;

    if (tid < 128) {
        s_m[tid]  = rm[z * S_ + m0 + tid];
        s_il[tid] = 1.0f / rl[z * S_ + m0 + tid];
    }

    const int lane = tid & 31, g = lane >> 2, tg = lane & 3;
    const int wid = tid >> 5, wm = wid & 3, wn = wid >> 2;

    float acc[2][4][4];
    #pragma unroll
    for (int i = 0; i < 2; i++)
        #pragma unroll
        for (int j = 0; j < 4; j++)
            #pragma unroll
            for (int t = 0; t < 4; t++) acc[i][j][t] = 0.f;

    const int r0 = tid >> 4;
    const int c4 = (tid & 15) * 4;
    const int kend = m0 + 128;

    for (int k0 = 0; k0 < kend; k0 += 64) {
        __syncthreads();   // protects smem reuse + first s_m use

        // P tile 128x64: read raw, mask + exp, tf32
        #pragma unroll
        for (int p = 0; p < 8; p++) {
            const int r = r0 + p * 16;
            const int ig = m0 + r;
            const float mi = s_m[r];
            const float il = s_il[r];
            const float4 v = *reinterpret_cast<const float4*>(
                &raw[roff + (size_t)ig * S_ + k0 + c4]);
            float pv[4] = {v.x, v.y, v.z, v.w};
            #pragma unroll
            for (int u = 0; u < 4; u++) {
                const int j = k0 + c4 + u;
                const float e = (j <= ig) ? __expf(pv[u] - mi) * il : 0.f;
                Ph[(c4 + u) * 132 + r] = f2tf32(e);
            }
        }
        // V tile 64x64: hi/lo split, [k][n] (no transpose)
        #pragma unroll
        for (int p = 0; p < 4; p++) {
            const int r = r0 + p * 16;
            const float4 v = *reinterpret_cast<const float4*>(
                &V[voff + (size_t)(k0 + r) * D_ + c4]);
            uint32_t hi, lo;
            split_tf32(v.x, hi, lo); Vh[r * 68 + c4 + 0] = hi; Vl[r * 68 + c4 + 0] = lo;
            split_tf32(v.y, hi, lo); Vh[r * 68 + c4 + 1] = hi; Vl[r * 68 + c4 + 1] = lo;
            split_tf32(v.z, hi, lo); Vh[r * 68 + c4 + 2] = hi; Vl[r * 68 + c4 + 2] = lo;
            split_tf32(v.w, hi, lo); Vh[r * 68 + c4 + 3] = hi; Vl[r * 68 + c4 + 3] = lo;
        }
        __syncthreads();

        #pragma unroll
        for (int ks = 0; ks < 8; ks++) {
            const int kb = ks * 8;
            uint32_t ph[2][4], vh[4][2], vl[4][2];
            #pragma unroll
            for (int mf = 0; mf < 2; mf++) {
                const int m = wm * 32 + mf * 16;
                ph[mf][0] = Ph[(kb + tg) * 132 + m + g];
                ph[mf][1] = Ph[(kb + tg) * 132 + m + 8 + g];
                ph[mf][2] = Ph[(kb + tg + 4) * 132 + m + g];
                ph[mf][3] = Ph[(kb + tg + 4) * 132 + m + 8 + g];
            }
            #pragma unroll
            for (int nf = 0; nf < 4; nf++) {
                const int n = wn * 32 + nf * 8 + g;
                vh[nf][0] = Vh[(kb + tg) * 68 + n];
                vh[nf][1] = Vh[(kb + tg + 4) * 68 + n];
                vl[nf][0] = Vl[(kb + tg) * 68 + n];
                vl[nf][1] = Vl[(kb + tg + 4) * 68 + n];
            }
            #pragma unroll
            for (int mf = 0; mf < 2; mf++)
                #pragma unroll
                for (int nf = 0; nf < 4; nf++) {
                    mma8(acc[mf][nf], ph[mf], vh[nf]);
                    mma8(acc[mf][nf], ph[mf], vl[nf]);
                }
        }
    }

    #pragma unroll
    for (int mf = 0; mf < 2; mf++) {
        const int rbase = m0 + wm * 32 + mf * 16 + g;
        #pragma unroll
        for (int nf = 0; nf < 4; nf++) {
            const int c = wn * 32 + nf * 8 + 2 * tg;
            float2 v0 = make_float2(acc[mf][nf][0], acc[mf][nf][1]);
            float2 v1 = make_float2(acc[mf][nf][2], acc[mf][nf][3]);
            *reinterpret_cast<float2*>(&ctx[(size_t)(b * S_ + rbase) * D_ + h * DH + c]) = v0;
            *reinterpret_cast<float2*>(&ctx[(size_t)(b * S_ + rbase + 8) * D_ + h * DH + c]) = v1;
        }
    }
}

// ---------------------------------------------------------------------------
// fp32 SIMT GEMM for projections: C = A@B + bias (128x128x16, 8x8 microtile)
// ---------------------------------------------------------------------------
__global__ __launch_bounds__(256)
void proj_kernel(const float* __restrict__ A,
                 const float* __restrict__ Bm,
                 const float* __restrict__ bias,
                 float* __restrict__ C, int K)
{
    __shared__ float As[16][128];
    __shared__ float Bs[16][128];

    const int tid = threadIdx.x;
    const int bx = blockIdx.x, by = blockIdx.y;

    const int trow = tid / 16;
    const int tcol = tid % 16;

    float acc[8][8];
    #pragma unroll
    for (int m = 0; m < 8; m++)
        #pragma unroll
        for (int n = 0; n < 8; n++) acc[m][n] = 0.f;

    const int aCol = tid % 4;     // float4 along K (BK=16 -> 4 float4)
    const int aRow0 = tid / 4;    // 64 rows per pass, 2 passes
    const int bCol = tid % 32;    // float4 along N
    const int bRow0 = tid / 32;   // 8 rows per pass, 2 passes

    for (int k0 = 0; k0 < K; k0 += 16) {
        __syncthreads();
        #pragma unroll
        for (int p = 0; p < 2; p++) {
            const int r = aRow0 + p * 64;
            const float4 av = *reinterpret_cast<const float4*>(
                &A[(size_t)(by * 128 + r) * K + k0 + aCol * 4]);
            As[aCol * 4 + 0][r] = av.x;
            As[aCol * 4 + 1][r] = av.y;
            As[aCol * 4 + 2][r] = av.z;
            As[aCol * 4 + 3][r] = av.w;
        }
        #pragma unroll
        for (int p = 0; p < 2; p++) {
            const int r = bRow0 + p * 8;
            const float4 bv = *reinterpret_cast<const float4*>(
                &Bm[(size_t)(k0 + r) * D_ + bx * 128 + bCol * 4]);
            *reinterpret_cast<float4*>(&Bs[r][bCol * 4]) = bv;
        }
        __syncthreads();

        #pragma unroll
        for (int kk = 0; kk < 16; ++kk) {
            float ra[8], rb[8];
            #pragma unroll
            for (int m = 0; m < 8; m += 4)
                *reinterpret_cast<float4*>(&ra[m]) =
                    *reinterpret_cast<const float4*>(&As[kk][trow * 8 + m]);
            #pragma unroll
            for (int n = 0; n < 8; n += 4)
                *reinterpret_cast<float4*>(&rb[n]) =
                    *reinterpret_cast<const float4*>(&Bs[kk][tcol * 8 + n]);
            #pragma unroll
            for (int m = 0; m < 8; m++)
                #pragma unroll
                for (int n = 0; n < 8; n++)
                    acc[m][n] += ra[m] * rb[n];
        }
    }

    #pragma unroll
    for (int m = 0; m < 8; m++) {
        const int gr = by * 128 + trow * 8 + m;
        const size_t base = (size_t)gr * D_ + bx * 128 + tcol * 8;
        #pragma unroll
        for (int n0 = 0; n0 < 8; n0 += 4) {
            const float4 bb = *reinterpret_cast<const float4*>(
                &bias[bx * 128 + tcol * 8 + n0]);
            float4 o;
            o.x = acc[m][n0 + 0] + bb.x;
            o.y = acc[m][n0 + 1] + bb.y;
            o.z = acc[m][n0 + 2] + bb.z;
            o.w = acc[m][n0 + 3] + bb.w;
            *reinterpret_cast<float4*>(&C[base + n0]) = o;
        }
    }
}

// ---------------------------------------------------------------------------
// Per-row causal softmax stats
// ---------------------------------------------------------------------------
__global__ __launch_bounds__(256)
void softmax_stats_kernel(const float* __restrict__ raw,
                          float* __restrict__ gm, float* __restrict__ gl)
{
    const int i = blockIdx.x;
    const int z = blockIdx.y;
    const float* row = raw + ((size_t)z * S_ + i) * (size_t)S_;
    const int tid = threadIdx.x;

    float v[16];
    #pragma unroll
    for (int t = 0; t < 4; t++) {
        const int j4 = t * 256 + tid;
        const float4 x = *reinterpret_cast<const float4*>(&row[j4 * 4]);
        const int j0 = j4 * 4;
        v[t * 4 + 0] = (j0 + 0 <= i) ? x.x : -CUDART_INF_F;
        v[t * 4 + 1] = (j0 + 1 <= i) ? x.y : -CUDART_INF_F;
        v[t * 4 + 2] = (j0 + 2 <= i) ? x.z : -CUDART_INF_F;
        v[t * 4 + 3] = (j0 + 3 <= i) ? x.w : -CUDART_INF_F;
    }

    float lm = v[0];
    #pragma unroll
    for (int t = 1; t < 16; t++) lm = fmaxf(lm, v[t]);

    __shared__ float red[256];
    red[tid] = lm;
    __syncthreads();
    #pragma unroll
    for (int s = 128; s > 0; s >>= 1) {
        if (tid < s) red[tid] = fmaxf(red[tid], red[tid + s]);
        __syncthreads();
    }
    const float m = red[0];
    __syncthreads();

    float ls = 0.f;
    #pragma unroll
    for (int t = 0; t < 16; t++) ls += __expf(v[t] - m);
    red[tid] = ls;
    __syncthreads();
    #pragma unroll
    for (int s = 128; s > 0; s >>= 1) {
        if (tid < s) red[tid] += red[tid + s];
        __syncthreads();
    }
    if (tid == 0) {
        gm[(size_t)z * S_ + i] = m;
        gl[(size_t)z * S_ + i] = red[0];
    }
}

// ---------------------------------------------------------------------------
extern "C" void kernel_launch(void* const* d_in, const int* in_sizes, int n_in,
                              void* d_out, int out_size)
{
    const float* x  = (const float*)d_in[0];
    const float* Wq = (const float*)d_in[1];
    const float* bq = (const float*)d_in[2];
    const float* Wk = (const float*)d_in[3];
    const float* bk = (const float*)d_in[4];
    const float* Wv = (const float*)d_in[5];
    const float* bv = (const float*)d_in[6];
    const float* Wo = (const float*)d_in[7];
    const float* bo = (const float*)d_in[8];

    float* sa  = (float*)d_out;
    float* raw = (float*)d_out + SA_ELEMS;

    float *qp, *kp, *vp, *cp, *mp, *lp;
    cudaGetSymbolAddress((void**)&qp, g_q);
    cudaGetSymbolAddress((void**)&kp, g_k);
    cudaGetSymbolAddress((void**)&vp, g_v);
    cudaGetSymbolAddress((void**)&cp, g_ctx);
    cudaGetSymbolAddress((void**)&mp, g_m);
    cudaGetSymbolAddress((void**)&lp, g_l);

    static bool attr_done = false;
    if (!attr_done) {
        cudaFuncSetAttribute(scores_kernel,
                             cudaFuncAttributeMaxDynamicSharedMemorySize, 102400);
        cudaFuncSetAttribute(pv_kernel,
                             cudaFuncAttributeMaxDynamicSharedMemorySize, 69632);
        attr_done = true;
    }

    const dim3 blk(256);

    // QKV projections
    const dim3 gproj(D_ / 128, MR / 128, 1);
    proj_kernel<<<gproj, blk>>>(x, Wq, bq, qp, D_);
    proj_kernel<<<gproj, blk>>>(x, Wk, bk, kp, D_);
    proj_kernel<<<gproj, blk>>>(x, Wv, bv, vp, D_);

    // scores (tensor core, 3xTF32)
    scores_kernel<<<dim3(S_ / 64, S_ / 128, H_ * B_), blk, 102400>>>(qp, kp, raw);

    // softmax stats
    softmax_stats_kernel<<<dim3(S_, H_ * B_), blk>>>(raw, mp, lp);

    // PV (tensor core tf32)
    pv_kernel<<<dim3(1, S_ / 128, H_ * B_), blk, 69632>>>(raw, vp, mp, lp, cp);

    // output projection
    proj_kernel<<<gproj, blk>>>(cp, Wo, bo, sa, D_);
}

// round 3
// speedup vs baseline: 1.7962x; 1.7962x over previous
#include <cuda_runtime.h>
#include <cuda_bf16.h>
#include <math_constants.h>
#include <cstdint>

namespace {
constexpr int B_ = 2, S_ = 4096, D_ = 512, H_ = 8, DH = 64;
constexpr int MR = B_ * S_;
constexpr long long SA_ELEMS = (long long)MR * D_;
constexpr int ASTR = 132;   // words per A fragment-tile (128 + 4 pad)
constexpr int BSTR = 68;    // words per B fragment-tile (64 + 4 pad)
}

__device__ float g_q[MR * D_];
__device__ float g_k[MR * D_];
__device__ float g_v[MR * D_];
__device__ float g_ctx[MR * D_];
__device__ float g_m[H_ * B_ * S_];
__device__ float g_l[H_ * B_ * S_];

// ---------------------------------------------------------------------------
// helpers
// ---------------------------------------------------------------------------
__device__ __forceinline__ uint32_t pack_bf(float x, float y) {
    __nv_bfloat162 t = __floats2bfloat162_rn(x, y);   // .x = x (low half)
    return reinterpret_cast<uint32_t&>(t);
}
__device__ __forceinline__ void split2(float x, float y, uint32_t& hi, uint32_t& lo) {
    const float hx = __bfloat162float(__float2bfloat16_rn(x));
    const float hy = __bfloat162float(__float2bfloat16_rn(y));
    hi = pack_bf(hx, hy);
    lo = pack_bf(x - hx, y - hy);
}
__device__ __forceinline__ void mma16(float* d, const uint32_t* a, const uint32_t* b) {
    asm volatile(
        "mma.sync.aligned.m16n8k16.row.col.f32.bf16.bf16.f32 "
        "{%0,%1,%2,%3}, {%4,%5,%6,%7}, {%8,%9}, {%0,%1,%2,%3};"
        : "+f"(d[0]), "+f"(d[1]), "+f"(d[2]), "+f"(d[3])
        : "r"(a[0]), "r"(a[1]), "r"(a[2]), "r"(a[3]), "r"(b[0]), "r"(b[1]));
}

// store fp32x4 (row, cols c4..c4+3 of the 64-wide k-chunk) into A fragment-order
__device__ __forceinline__ void storeA(uint32_t* Ah, uint32_t* Al,
                                       int row, int c4, float4 v) {
    const int mt = row >> 4, rin = row & 15, g = rin & 7, hi8 = rin >> 3;
    const int ks = c4 >> 4, c16 = c4 & 15;
    const int tg = (c16 & 7) >> 1;
    const int reg = ((c16 < 8) ? 0 : 2) + hi8;
    uint32_t h0, l0, h1, l1;
    split2(v.x, v.y, h0, l0);
    split2(v.z, v.w, h1, l1);
    const int base = (mt * 4 + ks) * ASTR + (g * 4 + tg) * 4 + reg;
    Ah[base] = h0;     Al[base] = l0;
    Ah[base + 4] = h1; Al[base + 4] = l1;   // tg+1 lane
}

// B source row-major along k (row = n): scores K-matrix
__device__ __forceinline__ void storeB_rowk(uint32_t* Bh, uint32_t* Bl,
                                            int n, int c4, float4 v) {
    const int nt = n >> 3, g = n & 7;
    const int ks = c4 >> 4, k16 = c4 & 15;
    const int tg = (k16 & 7) >> 1;
    const int reg = (k16 < 8) ? 0 : 1;
    uint32_t h0, l0, h1, l1;
    split2(v.x, v.y, h0, l0);
    split2(v.z, v.w, h1, l1);
    const int base = (nt * 4 + ks) * BSTR + (g * 4 + tg) * 2 + reg;
    Bh[base] = h0;     Bl[base] = l0;
    Bh[base + 2] = h1; Bl[base + 2] = l1;   // tg+1 lane
}

// B source [k][n] n-contiguous: weights / V. a = row k, b = row k+1 (cols n4..n4+3)
__device__ __forceinline__ void storeB_kn(uint32_t* Bh, uint32_t* Bl,
                                          int k, int n4, float4 a, float4 b) {
    const int ks = k >> 4, k16 = k & 15;
    const int tg = (k16 & 7) >> 1;
    const int reg = (k16 < 8) ? 0 : 1;
    const float av[4] = {a.x, a.y, a.z, a.w};
    const float bv[4] = {b.x, b.y, b.z, b.w};
    #pragma unroll
    for (int j = 0; j < 4; j++) {
        const int n = n4 + j, nt = n >> 3, g = n & 7;
        uint32_t h, l;
        split2(av[j], bv[j], h, l);
        const int w = (nt * 4 + ks) * BSTR + (g * 4 + tg) * 2 + reg;
        Bh[w] = h; Bl[w] = l;
    }
}

// one 64-deep k-chunk of bf16 3-product mma
template<int MF, int NF>
__device__ __forceinline__ void compute_chunk(
    const uint32_t* __restrict__ Ah, const uint32_t* __restrict__ Al,
    const uint32_t* __restrict__ Bh, const uint32_t* __restrict__ Bl,
    int mtbase, int ntbase, int lane, float (&acc)[MF][NF][4])
{
    #pragma unroll
    for (int ks = 0; ks < 4; ks++) {
        uint32_t bh[NF][2], bl[NF][2];
        #pragma unroll
        for (int nf = 0; nf < NF; nf++) {
            const int w = ((ntbase + nf) * 4 + ks) * BSTR + lane * 2;
            const uint2 h = *reinterpret_cast<const uint2*>(Bh + w);
            const uint2 l = *reinterpret_cast<const uint2*>(Bl + w);
            bh[nf][0] = h.x; bh[nf][1] = h.y;
            bl[nf][0] = l.x; bl[nf][1] = l.y;
        }
        #pragma unroll
        for (int mf = 0; mf < MF; mf++) {
            const int w = ((mtbase + mf) * 4 + ks) * ASTR + lane * 4;
            const uint4 ha = *reinterpret_cast<const uint4*>(Ah + w);
            const uint4 la = *reinterpret_cast<const uint4*>(Al + w);
            const uint32_t ah[4] = {ha.x, ha.y, ha.z, ha.w};
            const uint32_t al[4] = {la.x, la.y, la.z, la.w};
            #pragma unroll
            for (int nf = 0; nf < NF; nf++) {
                mma16(acc[mf][nf], ah, bh[nf]);
                mma16(acc[mf][nf], al, bh[nf]);
                mma16(acc[mf][nf], ah, bl[nf]);
            }
        }
    }
}

// ---------------------------------------------------------------------------
// Scores: raw[z] = (Q_z @ K_z^T)/8, full SxS. Block 128x128, K=64 one-shot.
// 8 warps: wm = wid&1 (64 rows), wn = wid>>1 (32 cols).
// ---------------------------------------------------------------------------
__global__ __launch_bounds__(256, 2)
void scores_kernel(const float* __restrict__ Q, const float* __restrict__ K,
                   float* __restrict__ raw)
{
    extern __shared__ uint32_t sm[];
    uint32_t* Ah = sm;
    uint32_t* Al = Ah + 32 * ASTR;
    uint32_t* Bh = Al + 32 * ASTR;
    uint32_t* Bl = Bh + 64 * BSTR;

    const int tid = threadIdx.x;
    const int z = blockIdx.z, h = z >> 1, b = z & 1;
    const int m0 = blockIdx.y * 128;
    const int n0 = blockIdx.x * 128;
    const size_t qoff = (size_t)b * S_ * D_ + (size_t)h * DH;

    #pragma unroll
    for (int p = 0; p < 8; p++) {
        const int idx = tid + p * 256;
        const int r = idx >> 4, c4 = (idx & 15) * 4;
        const float4 qv = *reinterpret_cast<const float4*>(
            &Q[qoff + (size_t)(m0 + r) * D_ + c4]);
        storeA(Ah, Al, r, c4, qv);
        const float4 kv = *reinterpret_cast<const float4*>(
            &K[qoff + (size_t)(n0 + r) * D_ + c4]);
        storeB_rowk(Bh, Bl, r, c4, kv);
    }
    __syncthreads();

    const int lane = tid & 31, g = lane >> 2, tg = lane & 3;
    const int wid = tid >> 5, wm = wid & 1, wn = wid >> 1;

    float acc[4][4][4];
    #pragma unroll
    for (int i = 0; i < 4; i++)
        #pragma unroll
        for (int j = 0; j < 4; j++)
            #pragma unroll
            for (int t = 0; t < 4; t++) acc[i][j][t] = 0.f;

    compute_chunk<4, 4>(Ah, Al, Bh, Bl, wm * 4, wn * 4, lane, acc);

    float* out = raw + (size_t)z * S_ * S_;
    #pragma unroll
    for (int mf = 0; mf < 4; mf++) {
        const int row = m0 + wm * 64 + mf * 16 + g;
        #pragma unroll
        for (int nf = 0; nf < 4; nf++) {
            const int col = n0 + wn * 32 + nf * 8 + 2 * tg;
            *reinterpret_cast<float2*>(&out[(size_t)row * S_ + col]) =
                make_float2(acc[mf][nf][0] * 0.125f, acc[mf][nf][1] * 0.125f);
            *reinterpret_cast<float2*>(&out[(size_t)(row + 8) * S_ + col]) =
                make_float2(acc[mf][nf][2] * 0.125f, acc[mf][nf][3] * 0.125f);
        }
    }
}

// ---------------------------------------------------------------------------
// Projection: C[M=8192,N=512] = A[M,512] @ W[512,512] + bias. Block 128x128.
// ---------------------------------------------------------------------------
__global__ __launch_bounds__(256, 2)
void proj_kernel(const float* __restrict__ A, const float* __restrict__ W,
                 const float* __restrict__ bias, float* __restrict__ C)
{
    extern __shared__ uint32_t sm[];
    uint32_t* Ah = sm;
    uint32_t* Al = Ah + 32 * ASTR;
    uint32_t* Bh = Al + 32 * ASTR;
    uint32_t* Bl = Bh + 64 * BSTR;

    const int tid = threadIdx.x;
    const int m0 = blockIdx.y * 128;
    const int n0 = blockIdx.x * 128;

    const int lane = tid & 31, g = lane >> 2, tg = lane & 3;
    const int wid = tid >> 5, wm = wid & 1, wn = wid >> 1;

    float acc[4][4][4];
    #pragma unroll
    for (int i = 0; i < 4; i++)
        #pragma unroll
        for (int j = 0; j < 4; j++)
            #pragma unroll
            for (int t = 0; t < 4; t++) acc[i][j][t] = 0.f;

    for (int kc = 0; kc < D_ / 64; kc++) {
        __syncthreads();
        #pragma unroll
        for (int p = 0; p < 8; p++) {
            const int idx = tid + p * 256;
            const int r = idx >> 4, c4 = (idx & 15) * 4;
            const float4 av = *reinterpret_cast<const float4*>(
                &A[(size_t)(m0 + r) * D_ + kc * 64 + c4]);
            storeA(Ah, Al, r, c4, av);
        }
        #pragma unroll
        for (int p = 0; p < 4; p++) {
            const int idx = tid + p * 256;
            const int kp = idx >> 5, n4 = (idx & 31) * 4;
            const int krow = kc * 64 + 2 * kp;
            const float4 w0 = *reinterpret_cast<const float4*>(
                &W[(size_t)krow * D_ + n0 + n4]);
            const float4 w1 = *reinterpret_cast<const float4*>(
                &W[(size_t)(krow + 1) * D_ + n0 + n4]);
            storeB_kn(Bh, Bl, 2 * kp, n4, w0, w1);
        }
        __syncthreads();
        compute_chunk<4, 4>(Ah, Al, Bh, Bl, wm * 4, wn * 4, lane, acc);
    }

    #pragma unroll
    for (int mf = 0; mf < 4; mf++) {
        const int row = m0 + wm * 64 + mf * 16 + g;
        #pragma unroll
        for (int nf = 0; nf < 4; nf++) {
            const int col = n0 + wn * 32 + nf * 8 + 2 * tg;
            const float2 bb = *reinterpret_cast<const float2*>(&bias[col]);
            *reinterpret_cast<float2*>(&C[(size_t)row * D_ + col]) =
                make_float2(acc[mf][nf][0] + bb.x, acc[mf][nf][1] + bb.y);
            *reinterpret_cast<float2*>(&C[(size_t)(row + 8) * D_ + col]) =
                make_float2(acc[mf][nf][2] + bb.x, acc[mf][nf][3] + bb.y);
        }
    }
}

// ---------------------------------------------------------------------------
// PV: ctx = softmax(raw) @ V (causal). Block 128 rows x 64 cols, k-chunks 64.
// 8 warps: wm = wid&3 (32 rows), wn = wid>>2 (32 cols). MF=2, NF=4.
// ---------------------------------------------------------------------------
__global__ __launch_bounds__(256, 2)
void pv_kernel(const float* __restrict__ raw, const float* __restrict__ V,
               const float* __restrict__ rm, const float* __restrict__ rl,
               float* __restrict__ ctx)
{
    extern __shared__ uint32_t sm[];
    uint32_t* Ah = sm;
    uint32_t* Al = Ah + 32 * ASTR;
    uint32_t* Bh = Al + 32 * ASTR;
    uint32_t* Bl = Bh + 32 * BSTR;
    float* s_m  = reinterpret_cast<float*>(Bl + 32 * BSTR);
    float* s_il = s_m + 128;

    const int tid = threadIdx.x;
    const int z = blockIdx.z, h = z >> 1, b = z & 1;
    const int m0 = (int)(gridDim.y - 1 - blockIdx.y) * 128;   // heavy first
    const size_t roff = (size_t)z * S_ * S_;
    const size_t voff = (size_t)b * S_ * D_ + (size_t)h * DH;

    if (tid < 128) {
        s_m[tid]  = rm[z * S_ + m0 + tid];
        s_il[tid] = 1.0f / rl[z * S_ + m0 + tid];
    }

    const int lane = tid & 31, g = lane >> 2, tg = lane & 3;
    const int wid = tid >> 5, wm = wid & 3, wn = wid >> 2;

    float acc[2][4][4];
    #pragma unroll
    for (int i = 0; i < 2; i++)
        #pragma unroll
        for (int j = 0; j < 4; j++)
            #pragma unroll
            for (int t = 0; t < 4; t++) acc[i][j][t] = 0.f;

    const int kend = m0 + 128;
    for (int k0 = 0; k0 < kend; k0 += 64) {
        __syncthreads();
        #pragma unroll
        for (int p = 0; p < 8; p++) {
            const int idx = tid + p * 256;
            const int r = idx >> 4, c4 = (idx & 15) * 4;
            const int ig = m0 + r;
            const float mi = s_m[r], il = s_il[r];
            const float4 x = *reinterpret_cast<const float4*>(
                &raw[roff + (size_t)ig * S_ + k0 + c4]);
            float4 e;
            e.x = (k0 + c4 + 0 <= ig) ? __expf(x.x - mi) * il : 0.f;
            e.y = (k0 + c4 + 1 <= ig) ? __expf(x.y - mi) * il : 0.f;
            e.z = (k0 + c4 + 2 <= ig) ? __expf(x.z - mi) * il : 0.f;
            e.w = (k0 + c4 + 3 <= ig) ? __expf(x.w - mi) * il : 0.f;
            storeA(Ah, Al, r, c4, e);
        }
        #pragma unroll
        for (int p = 0; p < 2; p++) {
            const int idx = tid + p * 256;
            const int kp = idx >> 4, n4 = (idx & 15) * 4;
            const int krow = k0 + 2 * kp;
            const float4 v0 = *reinterpret_cast<const float4*>(
                &V[voff + (size_t)krow * D_ + n4]);
            const float4 v1 = *reinterpret_cast<const float4*>(
                &V[voff + (size_t)(krow + 1) * D_ + n4]);
            storeB_kn(Bh, Bl, 2 * kp, n4, v0, v1);
        }
        __syncthreads();
        compute_chunk<2, 4>(Ah, Al, Bh, Bl, wm * 2, wn * 4, lane, acc);
    }

    #pragma unroll
    for (int mf = 0; mf < 2; mf++) {
        const int row = m0 + wm * 32 + mf * 16 + g;
        #pragma unroll
        for (int nf = 0; nf < 4; nf++) {
            const int col = wn * 32 + nf * 8 + 2 * tg;
            *reinterpret_cast<float2*>(
                &ctx[(size_t)(b * S_ + row) * D_ + h * DH + col]) =
                make_float2(acc[mf][nf][0], acc[mf][nf][1]);
            *reinterpret_cast<float2*>(
                &ctx[(size_t)(b * S_ + row + 8) * D_ + h * DH + col]) =
                make_float2(acc[mf][nf][2], acc[mf][nf][3]);
        }
    }
}

// ---------------------------------------------------------------------------
// Online causal softmax stats (single pass over j <= i)
// ---------------------------------------------------------------------------
__global__ __launch_bounds__(256)
void stats_kernel(const float* __restrict__ raw,
                  float* __restrict__ gm, float* __restrict__ gl)
{
    const int i = blockIdx.x, z = blockIdx.y;
    const float* row = raw + ((size_t)z * S_ + i) * (size_t)S_;
    const int tid = threadIdx.x;

    float m = -CUDART_INF_F, s = 0.f;
    for (int j = tid * 4; j <= i; j += 1024) {
        const float4 x = *reinterpret_cast<const float4*>(&row[j]);
        const float xs[4] = {x.x, x.y, x.z, x.w};
        float cm = m;
        #pragma unroll
        for (int u = 0; u < 4; u++)
            if (j + u <= i) cm = fmaxf(cm, xs[u]);
        if (cm > m) { s *= __expf(m - cm); m = cm; }
        #pragma unroll
        for (int u = 0; u < 4; u++)
            if (j + u <= i) s += __expf(xs[u] - m);
    }

    __shared__ float rdm[256], rds[256];
    rdm[tid] = m; rds[tid] = s;
    __syncthreads();
    #pragma unroll
    for (int st = 128; st > 0; st >>= 1) {
        if (tid < st) {
            const float m2 = rdm[tid + st], s2 = rds[tid + st];
            const float M = fmaxf(rdm[tid], m2);
            float sn = 0.f;
            if (M != -CUDART_INF_F)
                sn = rds[tid] * __expf(rdm[tid] - M) + s2 * __expf(m2 - M);
            rdm[tid] = M; rds[tid] = sn;
        }
        __syncthreads();
    }
    if (tid == 0) {
        gm[(size_t)z * S_ + i] = rdm[0];
        gl[(size_t)z * S_ + i] = rds[0];
    }
}

// ---------------------------------------------------------------------------
extern "C" void kernel_launch(void* const* d_in, const int* in_sizes, int n_in,
                              void* d_out, int out_size)
{
    const float* x  = (const float*)d_in[0];
    const float* Wq = (const float*)d_in[1];
    const float* bq = (const float*)d_in[2];
    const float* Wk = (const float*)d_in[3];
    const float* bk = (const float*)d_in[4];
    const float* Wv = (const float*)d_in[5];
    const float* bv = (const float*)d_in[6];
    const float* Wo = (const float*)d_in[7];
    const float* bo = (const float*)d_in[8];

    float* sa  = (float*)d_out;
    float* raw = (float*)d_out + SA_ELEMS;

    float *qp, *kp, *vp, *cp, *mp, *lp;
    cudaGetSymbolAddress((void**)&qp, g_q);
    cudaGetSymbolAddress((void**)&kp, g_k);
    cudaGetSymbolAddress((void**)&vp, g_v);
    cudaGetSymbolAddress((void**)&cp, g_ctx);
    cudaGetSymbolAddress((void**)&mp, g_m);
    cudaGetSymbolAddress((void**)&lp, g_l);

    // smem sizes (bytes)
    const int smem_big = (2 * 32 * ASTR + 2 * 64 * BSTR) * 4;            // 68608
    const int smem_pv  = (2 * 32 * ASTR + 2 * 32 * BSTR) * 4 + 256 * 4;  // 52224

    cudaFuncSetAttribute(scores_kernel, cudaFuncAttributeMaxDynamicSharedMemorySize, smem_big);
    cudaFuncSetAttribute(proj_kernel,   cudaFuncAttributeMaxDynamicSharedMemorySize, smem_big);
    cudaFuncSetAttribute(pv_kernel,     cudaFuncAttributeMaxDynamicSharedMemorySize, smem_pv);

    const dim3 blk(256);
    const dim3 gproj(D_ / 128, MR / 128);

    proj_kernel<<<gproj, blk, smem_big>>>(x, Wq, bq, qp);
    proj_kernel<<<gproj, blk, smem_big>>>(x, Wk, bk, kp);
    proj_kernel<<<gproj, blk, smem_big>>>(x, Wv, bv, vp);

    scores_kernel<<<dim3(S_ / 128, S_ / 128, H_ * B_), blk, smem_big>>>(qp, kp, raw);

    stats_kernel<<<dim3(S_, H_ * B_), blk>>>(raw, mp, lp);

    pv_kernel<<<dim3(1, S_ / 128, H_ * B_), blk, smem_pv>>>(raw, vp, mp, lp, cp);

    proj_kernel<<<gproj, blk, smem_big>>>(cp, Wo, bo, sa);
}

// round 4
// speedup vs baseline: 2.2347x; 1.2441x over previous
#include <cuda_runtime.h>
#include <cuda_bf16.h>
#include <math_constants.h>
#include <cstdint>

namespace {
constexpr int B_ = 2, S_ = 4096, D_ = 512, H_ = 8, DH = 64;
constexpr int MR = B_ * S_;
constexpr long long SA_ELEMS = (long long)MR * D_;
constexpr int ASTR = 132;
constexpr int BSTR = 68;
}

// packed bf16-pair scratch (u32 = (bf16 lo-half, bf16 hi-half) of an adjacent pair)
__device__ uint32_t g_xh[MR * D_ / 2], g_xl[MR * D_ / 2];
__device__ uint32_t g_qh[MR * D_ / 2], g_ql[MR * D_ / 2];
__device__ uint32_t g_kh[MR * D_ / 2], g_kl[MR * D_ / 2];
__device__ uint32_t g_ch[MR * D_ / 2], g_cl[MR * D_ / 2];
__device__ uint32_t g_vh[MR * D_ / 2];                      // packed along rows (k)
__device__ float    g_v[MR * D_];
__device__ uint32_t g_wqh[D_ * D_ / 2], g_wql[D_ * D_ / 2];
__device__ uint32_t g_wkh[D_ * D_ / 2], g_wkl[D_ * D_ / 2];
__device__ uint32_t g_wvh[D_ * D_ / 2], g_wvl[D_ * D_ / 2];
__device__ uint32_t g_woh[D_ * D_ / 2], g_wol[D_ * D_ / 2];

// ---------------------------------------------------------------------------
__device__ __forceinline__ uint32_t pack_bf(float x, float y) {
    __nv_bfloat162 t = __floats2bfloat162_rn(x, y);
    return reinterpret_cast<uint32_t&>(t);
}
__device__ __forceinline__ void split2(float x, float y, uint32_t& hi, uint32_t& lo) {
    const float hx = __bfloat162float(__float2bfloat16_rn(x));
    const float hy = __bfloat162float(__float2bfloat16_rn(y));
    hi = pack_bf(hx, hy);
    lo = pack_bf(x - hx, y - hy);
}
__device__ __forceinline__ void mma16(float* d, const uint32_t* a, const uint32_t* b) {
    asm volatile(
        "mma.sync.aligned.m16n8k16.row.col.f32.bf16.bf16.f32 "
        "{%0,%1,%2,%3}, {%4,%5,%6,%7}, {%8,%9}, {%0,%1,%2,%3};"
        : "+f"(d[0]), "+f"(d[1]), "+f"(d[2]), "+f"(d[3])
        : "r"(a[0]), "r"(a[1]), "r"(a[2]), "r"(a[3]), "r"(b[0]), "r"(b[1]));
}

// 3-product bf16 chunk (hi/lo both sides), K=64
template<int MF, int NF>
__device__ __forceinline__ void compute_chunk3(
    const uint32_t* __restrict__ Ah, const uint32_t* __restrict__ Al,
    const uint32_t* __restrict__ Bh, const uint32_t* __restrict__ Bl,
    int mtbase, int ntbase, int lane, float (&acc)[MF][NF][4])
{
    #pragma unroll
    for (int ks = 0; ks < 4; ks++) {
        uint32_t bh[NF][2], bl[NF][2];
        #pragma unroll
        for (int nf = 0; nf < NF; nf++) {
            const int w = ((ntbase + nf) * 4 + ks) * BSTR + lane * 2;
            const uint2 h = *reinterpret_cast<const uint2*>(Bh + w);
            const uint2 l = *reinterpret_cast<const uint2*>(Bl + w);
            bh[nf][0] = h.x; bh[nf][1] = h.y;
            bl[nf][0] = l.x; bl[nf][1] = l.y;
        }
        #pragma unroll
        for (int mf = 0; mf < MF; mf++) {
            const int w = ((mtbase + mf) * 4 + ks) * ASTR + lane * 4;
            const uint4 ha = *reinterpret_cast<const uint4*>(Ah + w);
            const uint4 la = *reinterpret_cast<const uint4*>(Al + w);
            const uint32_t ah[4] = {ha.x, ha.y, ha.z, ha.w};
            const uint32_t al[4] = {la.x, la.y, la.z, la.w};
            #pragma unroll
            for (int nf = 0; nf < NF; nf++) {
                mma16(acc[mf][nf], ah, bh[nf]);
                mma16(acc[mf][nf], al, bh[nf]);
                mma16(acc[mf][nf], ah, bl[nf]);
            }
        }
    }
}

// ---------------------------------------------------------------------------
// pack kernels
// ---------------------------------------------------------------------------
__global__ __launch_bounds__(256)
void packA_kernel(const float* __restrict__ in, uint32_t* __restrict__ oh,
                  uint32_t* __restrict__ ol, int n4)
{
    const int i = blockIdx.x * 256 + threadIdx.x;
    if (i >= n4) return;
    const float4 v = reinterpret_cast<const float4*>(in)[i];
    uint32_t h0, l0, h1, l1;
    split2(v.x, v.y, h0, l0);
    split2(v.z, v.w, h1, l1);
    oh[2 * i] = h0; oh[2 * i + 1] = h1;
    ol[2 * i] = l0; ol[2 * i + 1] = l1;
}

template<bool LO>
__global__ __launch_bounds__(256)
void packB_kernel(const float* __restrict__ in, uint32_t* __restrict__ oh,
                  uint32_t* __restrict__ ol, int K)
{
    const int i = blockIdx.x * 256 + threadIdx.x;
    if (i >= (K / 2) * (D_ / 4)) return;
    const int kp = i >> 7, n4 = (i & 127) * 4;
    const float4 a = *reinterpret_cast<const float4*>(&in[(size_t)(2 * kp) * D_ + n4]);
    const float4 b = *reinterpret_cast<const float4*>(&in[(size_t)(2 * kp + 1) * D_ + n4]);
    const float av[4] = {a.x, a.y, a.z, a.w};
    const float bv[4] = {b.x, b.y, b.z, b.w};
    #pragma unroll
    for (int j = 0; j < 4; j++) {
        uint32_t h, l;
        split2(av[j], bv[j], h, l);
        oh[(size_t)kp * D_ + n4 + j] = h;
        if (LO) ol[(size_t)kp * D_ + n4 + j] = l;
    }
}

// ---------------------------------------------------------------------------
// Scores: raw = (Q@K^T)/8, packed bf16 inputs. Block 128x128, K=64 one-shot.
// ---------------------------------------------------------------------------
__global__ __launch_bounds__(256, 2)
void scores_kernel(const uint32_t* __restrict__ qh, const uint32_t* __restrict__ ql,
                   const uint32_t* __restrict__ kh, const uint32_t* __restrict__ kl,
                   float* __restrict__ raw)
{
    extern __shared__ uint32_t sm[];
    uint32_t* Ah = sm;
    uint32_t* Al = Ah + 32 * ASTR;
    uint32_t* Bh = Al + 32 * ASTR;
    uint32_t* Bl = Bh + 64 * BSTR;

    const int tid = threadIdx.x;
    const int z = blockIdx.z, h = z >> 1, b = z & 1;
    const int m0 = blockIdx.y * 128;
    const int n0 = blockIdx.x * 128;
    const size_t prow = (size_t)b * S_ * (D_ / 2) + h * (DH / 2);  // word offset of head

    #pragma unroll
    for (int p = 0; p < 8; p++) {
        const int idx = tid + p * 256;
        const int r = idx >> 4, w2 = (idx & 15) * 2;
        const int c4 = w2 * 2;
        // fragment positions
        const int mt = r >> 4, rin = r & 15, g = rin & 7, hi8 = rin >> 3;
        const int ks = c4 >> 4, c16 = c4 & 15;
        const int tg = (c16 & 7) >> 1;
        {   // A (Q)
            const size_t gw = prow + (size_t)(m0 + r) * (D_ / 2) + w2;
            const uint2 qh2 = *reinterpret_cast<const uint2*>(qh + gw);
            const uint2 ql2 = *reinterpret_cast<const uint2*>(ql + gw);
            const int reg = ((c16 < 8) ? 0 : 2) + hi8;
            const int base = (mt * 4 + ks) * ASTR + (g * 4 + tg) * 4 + reg;
            Ah[base] = qh2.x; Ah[base + 4] = qh2.y;
            Al[base] = ql2.x; Al[base + 4] = ql2.y;
        }
        {   // B (K), row = n
            const size_t gw = prow + (size_t)(n0 + r) * (D_ / 2) + w2;
            const uint2 kh2 = *reinterpret_cast<const uint2*>(kh + gw);
            const uint2 kl2 = *reinterpret_cast<const uint2*>(kl + gw);
            const int nt = r >> 3, gg = r & 7;
            const int reg = (c16 < 8) ? 0 : 1;
            const int base = (nt * 4 + ks) * BSTR + (gg * 4 + tg) * 2 + reg;
            Bh[base] = kh2.x; Bh[base + 2] = kh2.y;
            Bl[base] = kl2.x; Bl[base + 2] = kl2.y;
        }
    }
    __syncthreads();

    const int lane = tid & 31, g = lane >> 2, tg = lane & 3;
    const int wid = tid >> 5, wm = wid & 1, wn = wid >> 1;

    float acc[4][4][4];
    #pragma unroll
    for (int i = 0; i < 4; i++)
        #pragma unroll
        for (int j = 0; j < 4; j++)
            #pragma unroll
            for (int t = 0; t < 4; t++) acc[i][j][t] = 0.f;

    compute_chunk3<4, 4>(Ah, Al, Bh, Bl, wm * 4, wn * 4, lane, acc);

    float* out = raw + (size_t)z * S_ * S_;
    #pragma unroll
    for (int mf = 0; mf < 4; mf++) {
        const int row = m0 + wm * 64 + mf * 16 + g;
        #pragma unroll
        for (int nf = 0; nf < 4; nf++) {
            const int col = n0 + wn * 32 + nf * 8 + 2 * tg;
            *reinterpret_cast<float2*>(&out[(size_t)row * S_ + col]) =
                make_float2(acc[mf][nf][0] * 0.125f, acc[mf][nf][1] * 0.125f);
            *reinterpret_cast<float2*>(&out[(size_t)(row + 8) * S_ + col]) =
                make_float2(acc[mf][nf][2] * 0.125f, acc[mf][nf][3] * 0.125f);
        }
    }
}

// ---------------------------------------------------------------------------
// Projection (packed A, packed B): OUT=0 -> fp32 + bias; OUT=1 -> packedA + bias
// ---------------------------------------------------------------------------
template<int OUT>
__global__ __launch_bounds__(256, 2)
void proj_kernel(const uint32_t* __restrict__ ah_, const uint32_t* __restrict__ al_,
                 const uint32_t* __restrict__ bh_, const uint32_t* __restrict__ bl_,
                 const float* __restrict__ bias,
                 float* __restrict__ outf,
                 uint32_t* __restrict__ outh, uint32_t* __restrict__ outl)
{
    extern __shared__ uint32_t sm[];
    uint32_t* Ah = sm;
    uint32_t* Al = Ah + 32 * ASTR;
    uint32_t* Bh = Al + 32 * ASTR;
    uint32_t* Bl = Bh + 64 * BSTR;

    const int tid = threadIdx.x;
    const int m0 = blockIdx.y * 128;
    const int n0 = blockIdx.x * 128;

    const int lane = tid & 31, g = lane >> 2, tg = lane & 3;
    const int wid = tid >> 5, wm = wid & 1, wn = wid >> 1;

    float acc[4][4][4];
    #pragma unroll
    for (int i = 0; i < 4; i++)
        #pragma unroll
        for (int j = 0; j < 4; j++)
            #pragma unroll
            for (int t = 0; t < 4; t++) acc[i][j][t] = 0.f;

    for (int kc = 0; kc < D_ / 64; kc++) {
        __syncthreads();
        #pragma unroll
        for (int p = 0; p < 8; p++) {
            const int idx = tid + p * 256;
            const int r = idx >> 4, w2 = (idx & 15) * 2;
            const int c4 = w2 * 2;
            const int mt = r >> 4, rin = r & 15, gg = rin & 7, hi8 = rin >> 3;
            const int ks = c4 >> 4, c16 = c4 & 15;
            const int tgl = (c16 & 7) >> 1;
            const size_t gw = (size_t)(m0 + r) * (D_ / 2) + kc * 32 + w2;
            const uint2 a2 = *reinterpret_cast<const uint2*>(ah_ + gw);
            const uint2 l2 = *reinterpret_cast<const uint2*>(al_ + gw);
            const int reg = ((c16 < 8) ? 0 : 2) + hi8;
            const int base = (mt * 4 + ks) * ASTR + (gg * 4 + tgl) * 4 + reg;
            Ah[base] = a2.x; Ah[base + 4] = a2.y;
            Al[base] = l2.x; Al[base + 4] = l2.y;
        }
        #pragma unroll
        for (int p = 0; p < 4; p++) {
            const int idx = tid + p * 256;
            const int kp = idx >> 5, n4 = (idx & 31) * 4;
            const int k = 2 * kp;
            const int ks = k >> 4, k16 = k & 15;
            const int tgl = (k16 & 7) >> 1;
            const int reg = (k16 < 8) ? 0 : 1;
            const size_t gw = (size_t)(kc * 32 + kp) * D_ + n0 + n4;
            const uint4 wh4 = *reinterpret_cast<const uint4*>(bh_ + gw);
            const uint4 wl4 = *reinterpret_cast<const uint4*>(bl_ + gw);
            const uint32_t hv[4] = {wh4.x, wh4.y, wh4.z, wh4.w};
            const uint32_t lv[4] = {wl4.x, wl4.y, wl4.z, wl4.w};
            #pragma unroll
            for (int j = 0; j < 4; j++) {
                const int n = n4 + j, nt = n >> 3, gg = n & 7;
                const int w = (nt * 4 + ks) * BSTR + (gg * 4 + tgl) * 2 + reg;
                Bh[w] = hv[j]; Bl[w] = lv[j];
            }
        }
        __syncthreads();
        compute_chunk3<4, 4>(Ah, Al, Bh, Bl, wm * 4, wn * 4, lane, acc);
    }

    #pragma unroll
    for (int mf = 0; mf < 4; mf++) {
        const int row = m0 + wm * 64 + mf * 16 + g;
        #pragma unroll
        for (int nf = 0; nf < 4; nf++) {
            const int col = n0 + wn * 32 + nf * 8 + 2 * tg;
            const float2 bb = *reinterpret_cast<const float2*>(&bias[col]);
            const float a0 = acc[mf][nf][0] + bb.x, a1 = acc[mf][nf][1] + bb.y;
            const float a2 = acc[mf][nf][2] + bb.x, a3 = acc[mf][nf][3] + bb.y;
            if (OUT == 0) {
                *reinterpret_cast<float2*>(&outf[(size_t)row * D_ + col]) = make_float2(a0, a1);
                *reinterpret_cast<float2*>(&outf[(size_t)(row + 8) * D_ + col]) = make_float2(a2, a3);
            } else {
                uint32_t h, l;
                split2(a0, a1, h, l);
                outh[(size_t)row * (D_ / 2) + (col >> 1)] = h;
                outl[(size_t)row * (D_ / 2) + (col >> 1)] = l;
                split2(a2, a3, h, l);
                outh[(size_t)(row + 8) * (D_ / 2) + (col >> 1)] = h;
                outl[(size_t)(row + 8) * (D_ / 2) + (col >> 1)] = l;
            }
        }
    }
}

// ---------------------------------------------------------------------------
// Fused flash PV: online softmax over causal raw, ctx = (softmax @ V), packedA out.
// Block: 128 rows x 64 (full DH), k-chunks of 64. Single bf16 product.
// ---------------------------------------------------------------------------
__global__ __launch_bounds__(256, 4)
void pv_fused_kernel(const float* __restrict__ raw, const uint32_t* __restrict__ vh,
                     uint32_t* __restrict__ ch, uint32_t* __restrict__ cl)
{
    __shared__ uint32_t Ph[32 * ASTR];
    __shared__ uint32_t Vh[32 * BSTR];
    __shared__ float s_m[128], s_s[128], s_scale[128];

    const int tid = threadIdx.x;
    const int z = blockIdx.z, h = z >> 1, b = z & 1;
    const int m0 = (int)(gridDim.y - 1 - blockIdx.y) * 128;
    const size_t roff = (size_t)z * S_ * S_;
    const size_t vbase = (size_t)(b * S_ / 2) * D_ + h * DH;   // word offset

    if (tid < 128) { s_m[tid] = -CUDART_INF_F; s_s[tid] = 0.f; }

    const int lane = tid & 31, g = lane >> 2, tg = lane & 3;
    const int wid = tid >> 5, wm = wid & 3, wn = wid >> 2;

    float acc[2][4][4];
    #pragma unroll
    for (int i = 0; i < 2; i++)
        #pragma unroll
        for (int j = 0; j < 4; j++)
            #pragma unroll
            for (int t = 0; t < 4; t++) acc[i][j][t] = 0.f;

    const int kend = m0 + 128;
    for (int k0 = 0; k0 < kend; k0 += 64) {
        __syncthreads();

        // ---- V tile 64x64 (hi only, pre-packed along k) ----
        #pragma unroll
        for (int p = 0; p < 2; p++) {
            const int idx = tid + p * 256;
            const int kp = idx >> 4, n4 = (idx & 15) * 4;
            const uint4 v = *reinterpret_cast<const uint4*>(
                &vh[vbase + (size_t)((k0 >> 1) + kp) * D_ + n4]);
            const int k16 = (2 * kp) & 15;
            const int tgl = (k16 & 7) >> 1;
            const int reg = (k16 < 8) ? 0 : 1;
            const int ks = kp >> 3;
            const uint32_t vv[4] = {v.x, v.y, v.z, v.w};
            #pragma unroll
            for (int j = 0; j < 4; j++) {
                const int n = n4 + j, nt = n >> 3, gg = n & 7;
                Vh[(nt * 4 + ks) * BSTR + (gg * 4 + tgl) * 2 + reg] = vv[j];
            }
        }

        // ---- P tile 128x64: mask, online stats, exp, bf16 ----
        #pragma unroll
        for (int p = 0; p < 8; p++) {
            const int idx = tid + p * 256;
            const int r = idx >> 4, c4 = (idx & 15) * 4;
            const int ig = m0 + r;
            const float4 x = *reinterpret_cast<const float4*>(
                &raw[roff + (size_t)ig * S_ + k0 + c4]);
            float xs[4] = {x.x, x.y, x.z, x.w};
            float cm = -CUDART_INF_F;
            #pragma unroll
            for (int u = 0; u < 4; u++) {
                if (k0 + c4 + u <= ig) cm = fmaxf(cm, xs[u]);
                else xs[u] = -CUDART_INF_F;
            }
            #pragma unroll
            for (int off = 8; off > 0; off >>= 1)
                cm = fmaxf(cm, __shfl_xor_sync(0xffffffffu, cm, off, 16));
            const float mold = s_m[r];
            const float mnew = fmaxf(mold, cm);
            float e[4], ls = 0.f;
            #pragma unroll
            for (int u = 0; u < 4; u++) {
                e[u] = (xs[u] == -CUDART_INF_F) ? 0.f : __expf(xs[u] - mnew);
                ls += e[u];
            }
            #pragma unroll
            for (int off = 8; off > 0; off >>= 1)
                ls += __shfl_xor_sync(0xffffffffu, ls, off, 16);
            if ((tid & 15) == 0) {
                const float sc = __expf(mold - mnew);   // mold=-inf only in chunk0 -> 0
                s_scale[r] = sc;
                s_m[r] = mnew;
                s_s[r] = s_s[r] * sc + ls;
            }
            const int mt = r >> 4, rin = r & 15, gg = rin & 7, hi8 = rin >> 3;
            const int ks = c4 >> 4, c16 = c4 & 15;
            const int tgl = (c16 & 7) >> 1;
            const int reg = ((c16 < 8) ? 0 : 2) + hi8;
            const int base = (mt * 4 + ks) * ASTR + (gg * 4 + tgl) * 4 + reg;
            Ph[base] = pack_bf(e[0], e[1]);
            Ph[base + 4] = pack_bf(e[2], e[3]);
        }
        __syncthreads();

        // ---- rescale accumulators ----
        float f[2][2];
        #pragma unroll
        for (int mf = 0; mf < 2; mf++) {
            const int row = wm * 32 + mf * 16;
            f[mf][0] = s_scale[row + g];
            f[mf][1] = s_scale[row + 8 + g];
        }
        #pragma unroll
        for (int mf = 0; mf < 2; mf++)
            #pragma unroll
            for (int nf = 0; nf < 4; nf++) {
                acc[mf][nf][0] *= f[mf][0]; acc[mf][nf][1] *= f[mf][0];
                acc[mf][nf][2] *= f[mf][1]; acc[mf][nf][3] *= f[mf][1];
            }

        // ---- single-product mma ----
        #pragma unroll
        for (int ks = 0; ks < 4; ks++) {
            uint32_t bf[4][2];
            #pragma unroll
            for (int nf = 0; nf < 4; nf++) {
                const int w = ((wn * 4 + nf) * 4 + ks) * BSTR + lane * 2;
                const uint2 hv = *reinterpret_cast<const uint2*>(Vh + w);
                bf[nf][0] = hv.x; bf[nf][1] = hv.y;
            }
            #pragma unroll
            for (int mf = 0; mf < 2; mf++) {
                const int w = ((wm * 2 + mf) * 4 + ks) * ASTR + lane * 4;
                const uint4 pa = *reinterpret_cast<const uint4*>(Ph + w);
                const uint32_t af[4] = {pa.x, pa.y, pa.z, pa.w};
                #pragma unroll
                for (int nf = 0; nf < 4; nf++)
                    mma16(acc[mf][nf], af, bf[nf]);
            }
        }
    }
    __syncthreads();

    // ---- epilogue: /l, pack to ctx ----
    #pragma unroll
    for (int mf = 0; mf < 2; mf++) {
        const int rl = wm * 32 + mf * 16;
        const float il0 = 1.0f / s_s[rl + g];
        const float il1 = 1.0f / s_s[rl + 8 + g];
        const int rowg = b * S_ + m0 + rl + g;
        #pragma unroll
        for (int nf = 0; nf < 4; nf++) {
            const int col = h * DH + wn * 32 + nf * 8 + 2 * tg;
            uint32_t hw, lw;
            split2(acc[mf][nf][0] * il0, acc[mf][nf][1] * il0, hw, lw);
            ch[(size_t)rowg * (D_ / 2) + (col >> 1)] = hw;
            cl[(size_t)rowg * (D_ / 2) + (col >> 1)] = lw;
            split2(acc[mf][nf][2] * il1, acc[mf][nf][3] * il1, hw, lw);
            ch[(size_t)(rowg + 8) * (D_ / 2) + (col >> 1)] = hw;
            cl[(size_t)(rowg + 8) * (D_ / 2) + (col >> 1)] = lw;
        }
    }
}

// ---------------------------------------------------------------------------
extern "C" void kernel_launch(void* const* d_in, const int* in_sizes, int n_in,
                              void* d_out, int out_size)
{
    const float* x  = (const float*)d_in[0];
    const float* Wq = (const float*)d_in[1];
    const float* bq = (const float*)d_in[2];
    const float* Wk = (const float*)d_in[3];
    const float* bk = (const float*)d_in[4];
    const float* Wv = (const float*)d_in[5];
    const float* bv = (const float*)d_in[6];
    const float* Wo = (const float*)d_in[7];
    const float* bo = (const float*)d_in[8];

    float* sa  = (float*)d_out;
    float* raw = (float*)d_out + SA_ELEMS;

    uint32_t *xh, *xl, *qh, *ql, *kh, *kl, *chp, *clp, *vhp;
    uint32_t *wqh, *wql, *wkh, *wkl, *wvh, *wvl, *woh, *wol;
    float* vfp;
    cudaGetSymbolAddress((void**)&xh, g_xh);   cudaGetSymbolAddress((void**)&xl, g_xl);
    cudaGetSymbolAddress((void**)&qh, g_qh);   cudaGetSymbolAddress((void**)&ql, g_ql);
    cudaGetSymbolAddress((void**)&kh, g_kh);   cudaGetSymbolAddress((void**)&kl, g_kl);
    cudaGetSymbolAddress((void**)&chp, g_ch);  cudaGetSymbolAddress((void**)&clp, g_cl);
    cudaGetSymbolAddress((void**)&vhp, g_vh);  cudaGetSymbolAddress((void**)&vfp, g_v);
    cudaGetSymbolAddress((void**)&wqh, g_wqh); cudaGetSymbolAddress((void**)&wql, g_wql);
    cudaGetSymbolAddress((void**)&wkh, g_wkh); cudaGetSymbolAddress((void**)&wkl, g_wkl);
    cudaGetSymbolAddress((void**)&wvh, g_wvh); cudaGetSymbolAddress((void**)&wvl, g_wvl);
    cudaGetSymbolAddress((void**)&woh, g_woh); cudaGetSymbolAddress((void**)&wol, g_wol);

    const int smem_big = (2 * 32 * ASTR + 2 * 64 * BSTR) * 4;
    cudaFuncSetAttribute(scores_kernel, cudaFuncAttributeMaxDynamicSharedMemorySize, smem_big);
    cudaFuncSetAttribute(proj_kernel<0>, cudaFuncAttributeMaxDynamicSharedMemorySize, smem_big);
    cudaFuncSetAttribute(proj_kernel<1>, cudaFuncAttributeMaxDynamicSharedMemorySize, smem_big);

    const dim3 blk(256);
    const dim3 gproj(D_ / 128, MR / 128);

    // pack inputs
    packA_kernel<<<(MR * D_ / 4 + 255) / 256, blk>>>(x, xh, xl, MR * D_ / 4);
    const int wthreads = (D_ / 2) * (D_ / 4);
    packB_kernel<true><<<(wthreads + 255) / 256, blk>>>(Wq, wqh, wql, D_);
    packB_kernel<true><<<(wthreads + 255) / 256, blk>>>(Wk, wkh, wkl, D_);
    packB_kernel<true><<<(wthreads + 255) / 256, blk>>>(Wv, wvh, wvl, D_);
    packB_kernel<true><<<(wthreads + 255) / 256, blk>>>(Wo, woh, wol, D_);

    // projections
    proj_kernel<1><<<gproj, blk, smem_big>>>(xh, xl, wqh, wql, bq, nullptr, qh, ql);
    proj_kernel<1><<<gproj, blk, smem_big>>>(xh, xl, wkh, wkl, bk, nullptr, kh, kl);
    proj_kernel<0><<<gproj, blk, smem_big>>>(xh, xl, wvh, wvl, bv, vfp, nullptr, nullptr);
    const int vthreads = (MR / 2) * (D_ / 4);
    packB_kernel<false><<<(vthreads + 255) / 256, blk>>>(vfp, vhp, nullptr, MR);

    // scores
    scores_kernel<<<dim3(S_ / 128, S_ / 128, H_ * B_), blk, smem_big>>>(qh, ql, kh, kl, raw);

    // fused softmax + PV
    pv_fused_kernel<<<dim3(1, S_ / 128, H_ * B_), blk>>>(raw, vhp, chp, clp);

    // output projection
    proj_kernel<0><<<gproj, blk, smem_big>>>(chp, clp, woh, wol, bo, sa, nullptr, nullptr);
}